// round 1
// baseline (speedup 1.0000x reference)
#include <cuda_runtime.h>
#include <math.h>

// out[i + offset] = x[i] with drop semantics  <=>  out[j] = (0 <= j-offset < n) ? x[j-offset] : 0
// offset = trunc(w_row + row_length * w_col), computed on-device from the scalar inputs.

__global__ void __launch_bounds__(256)
shift_kernel(const float* __restrict__ x,
             const float* __restrict__ w_row,
             const float* __restrict__ w_col,
             int row_length,
             int n,
             float4* __restrict__ out)
{
    // Scalar params: broadcast loads, hit L2/L1 for every warp after the first.
    const int offset = (int)(w_row[0] + (float)row_length * w_col[0]);

    const int j = (blockIdx.x * blockDim.x + threadIdx.x) << 2;  // base output idx (16B aligned)
    if (j >= n) return;

    const int s = j - offset;

    float4 v;
    {
        int s0 = s + 0;
        int s1 = s + 1;
        int s2 = s + 2;
        int s3 = s + 3;
        v.x = (s0 >= 0 && s0 < n) ? __ldg(x + s0) : 0.0f;
        v.y = (s1 >= 0 && s1 < n) ? __ldg(x + s1) : 0.0f;
        v.z = (s2 >= 0 && s2 < n) ? __ldg(x + s2) : 0.0f;
        v.w = (s3 >= 0 && s3 < n) ? __ldg(x + s3) : 0.0f;
    }

    out[j >> 2] = v;
}

extern "C" void kernel_launch(void* const* d_in, const int* in_sizes, int n_in,
                              void* d_out, int out_size)
{
    const float* x     = (const float*)d_in[0];
    const float* w_row = (const float*)d_in[1];
    const float* w_col = (const float*)d_in[2];

    const int n = in_sizes[0];
    // row_length: n = row_length^2 (8192 for this problem). Derive on host to
    // avoid depending on the integer input's on-device dtype.
    const int row_length = (int)(sqrt((double)n) + 0.5);

    const int threads = 256;
    const int vec = 4;
    const int blocks = (n + threads * vec - 1) / (threads * vec);

    shift_kernel<<<blocks, threads>>>(x, w_row, w_col, row_length, n, (float4*)d_out);
}